// round 15
// baseline (speedup 1.0000x reference)
#include <cuda_runtime.h>
#include <cstdint>

#define FULL 0xffffffffu

constexpr int   NTAG    = 32;
constexpr int   CH      = 8;              // steps per chunk
constexpr int   NS      = 4;              // phi ring slots (chunks)
constexpr int   STEPF   = NTAG * NTAG;    // 1024 floats per step
constexpr int   CHUNK_B = CH * STEPF * 4; // 32768 bytes
constexpr int   ARING   = 32;             // alpha ring slots (pow2)
constexpr float NEGINF  = -1e4f;

__device__ __forceinline__ void barsync() {
    asm volatile("bar.sync 0;" ::: "memory");
}

// bool-array accessor: mode 0 = int32, 1 = uint8, 2 = float32
__device__ __forceinline__ bool getb(const void* p, int idx, int mode) {
    if (mode == 0) return ((const int*)p)[idx] != 0;
    if (mode == 1) return ((const uint8_t*)p)[idx] != 0;
    return ((const float*)p)[idx] != 0.0f;
}

// load full 32-float alpha vector via 8 broadcast LDS.128
__device__ __forceinline__ void load_alpha(const float* __restrict__ aslot, float* a) {
    const uint4* q = (const uint4*)aslot;
#pragma unroll
    for (int k = 0; k < 8; ++k) {
        uint4 v = q[k];
        a[4*k+0] = __uint_as_float(v.x);
        a[4*k+1] = __uint_as_float(v.y);
        a[4*k+2] = __uint_as_float(v.z);
        a[4*k+3] = __uint_as_float(v.w);
    }
}

// Pair layout: float (i,j) of a step lives at byte offset (i>>1)*256 + j*8 + (i&1)*4.
// Lane j's pair pointer: (const float2*)stepbase + j; pair p at [p*32].

// ---- value-only step: max_i a[i] + (pht[i][j] [+ep]); pht = phi+tp pre-fused ----
template<bool END>
__device__ __forceinline__ float vval(const float2* __restrict__ ph2,
                                      const float* a, float epj)
{
    float s[NTAG];
#pragma unroll
    for (int p = 0; p < 16; ++p) {
        float2 e = ph2[p * 32];
        if (END) { e.x += epj; e.y += epj; }
        s[2*p]   = a[2*p]   + e.x;
        s[2*p+1] = a[2*p+1] + e.y;
    }
    float m[16];
#pragma unroll
    for (int k = 0; k < 16; ++k) m[k] = fmaxf(s[2*k], s[2*k+1]);
#pragma unroll
    for (int k = 0; k < 8; ++k)  m[k] = fmaxf(m[2*k], m[2*k+1]);
#pragma unroll
    for (int k = 0; k < 4; ++k)  m[k] = fmaxf(m[2*k], m[2*k+1]);
#pragma unroll
    for (int k = 0; k < 2; ++k)  m[k] = fmaxf(m[2*k], m[2*k+1]);
    return fmaxf(m[0], m[1]);
}

// ---- index-only step: first-argmax via left-biased select tree (identical op order) ----
template<bool END>
__device__ __forceinline__ int vidx(const float2* __restrict__ ph2,
                                    const float* a, float epj)
{
    float s[NTAG];
#pragma unroll
    for (int p = 0; p < 16; ++p) {
        float2 e = ph2[p * 32];
        if (END) { e.x += epj; e.y += epj; }
        s[2*p]   = a[2*p]   + e.x;
        s[2*p+1] = a[2*p+1] + e.y;
    }
    float v[16]; int ix[16];
#pragma unroll
    for (int k = 0; k < 16; ++k) {
        bool c = s[2*k+1] > s[2*k];
        v[k] = c ? s[2*k+1] : s[2*k];  ix[k] = c ? 2*k+1 : 2*k;
    }
#pragma unroll
    for (int k = 0; k < 8; ++k) {
        bool c = v[2*k+1] > v[2*k];
        v[k] = c ? v[2*k+1] : v[2*k];  ix[k] = c ? ix[2*k+1] : ix[2*k];
    }
#pragma unroll
    for (int k = 0; k < 4; ++k) {
        bool c = v[2*k+1] > v[2*k];
        v[k] = c ? v[2*k+1] : v[2*k];  ix[k] = c ? ix[2*k+1] : ix[2*k];
    }
#pragma unroll
    for (int k = 0; k < 2; ++k) {
        bool c = v[2*k+1] > v[2*k];
        v[k] = c ? v[2*k+1] : v[2*k];  ix[k] = c ? ix[2*k+1] : ix[2*k];
    }
    return (v[1] > v[0]) ? ix[1] : ix[0];
}

__global__ void __launch_bounds__(256, 1)
ConstrainedDecoder_kernel(const float* __restrict__ lp,
                          const void* __restrict__ mask,
                          const void* __restrict__ startc,
                          const void* __restrict__ endc,
                          const void* __restrict__ transc,
                          float* __restrict__ out,
                          int B, int T)
{
    extern __shared__ char smem[];
    float*   buf   = (float*)smem;                                       // NS*32KB phi ring (pair layout)
    float*   aring = (float*)(smem + NS * CHUNK_B);                      // ARING*32 floats
    uint8_t* back  = (uint8_t*)(smem + NS * CHUNK_B + ARING * NTAG * 4); // T*32 bytes
    int*     xsh   = (int*)(back + (size_t)T * NTAG);                    // final tag index

    const int b   = blockIdx.x;
    const int tid = threadIdx.x;
    const int j   = tid & 31;
    const int wid = tid >> 5;
    // wid 0: compute (SMSP0, private)   wid 4: idle (barrier only)
    // wid 1,2,5,6: argmax quarters       wid 3,7: producers

    // ---- detect bool encoding from mask[0] (guaranteed true) ----
    uint32_t w0 = ((const uint32_t*)mask)[0];
    const int mode = (w0 == 1u) ? 0 : (w0 == 0x01010101u) ? 1 : 2;

    // ---- sequence length (mask prefix-true); all warps compute it ----
    int len = 0;
    {
        const size_t mbase = (size_t)b * T;
        for (int k = j; k < T; k += 32)
            if (getb(mask, (int)(mbase + k), mode)) len = k + 1;
#pragma unroll
        for (int off = 16; off; off >>= 1)
            len = max(len, __shfl_xor_sync(FULL, len, off));
    }
    if (len < 1) len = 1;
    if (len > T) len = T;
    const int nchunk = (len + CH - 1) / CH;
    const int lenm1  = len - 1;

    if (wid == 3 || wid == 7) {
        // ============ producer warps (2): row-pair LDG -> fuse tp -> STS.64 pair layout ============
        const int p = (wid == 3) ? 0 : 1;   // pairs with q & 1 == p

        // row masks of transition constraints: lane i holds allowed-bits over j of row i
        uint32_t mytm = 0;
        for (int i = 0; i < NTAG; ++i) {
            uint32_t m = __ballot_sync(FULL, getb(transc, i * NTAG + j, mode));
            if (i == j) mytm = m;
        }

        const float* g = lp + (size_t)b * T * STEPF;
        float lo[64], hi[64];

        auto ldg = [&](int cc) {
            const float* gc = g + (size_t)cc * CH * STEPF + j;
#pragma unroll
            for (int k = 0; k < 64; ++k) {
                int q  = 2 * k + p;          // pair index within chunk (0..127)
                int t  = q >> 4;             // step within chunk
                int pq = q & 15;             // pair within step
                const float* base = gc + t * STEPF + pq * 64;
                lo[k] = base[0];             // row 2*pq
                hi[k] = base[32];            // row 2*pq+1
            }
        };
        auto sts = [&](int cc) {
            char* dstc = (char*)buf + (size_t)(cc & (NS - 1)) * CHUNK_B;
#pragma unroll
            for (int k = 0; k < 64; ++k) {
                int q  = 2 * k + p;
                int t  = q >> 4;
                int pq = q & 15;
                float flo = lo[k], fhi = hi[k];
                if (!(cc == 0 && t == 0)) {  // global step 0 stays raw (start step)
                    uint32_t m0 = __shfl_sync(FULL, mytm, 2 * pq);
                    uint32_t m1 = __shfl_sync(FULL, mytm, 2 * pq + 1);
                    flo += ((m0 >> j) & 1u) ? 0.0f : NEGINF;
                    fhi += ((m1 >> j) & 1u) ? 0.0f : NEGINF;
                }
                *(float2*)(dstc + (size_t)t * 4096 + (size_t)pq * 256 + (size_t)j * 8)
                    = make_float2(flo, fhi);
            }
        };

        ldg(0);
        sts(0);                    // startup: one exposed DRAM latency
        if (nchunk > 1) ldg(1);

        for (int c = 0; c <= nchunk; ++c) {
            barsync();             // phase c: compute consumes chunk c
            if (c + 1 < nchunk) {
                sts(c + 1);        // regs (loaded last phase) -> slot (c+1)%4
                if (c + 2 < nchunk) ldg(c + 2);
            }
        }
        barsync();                 // final output handoff
    } else if (wid == 0) {
        // ============ compute warp: value recurrence, private SMSP ============
        const float sp = getb(startc, j, mode) ? 0.0f : NEGINF;
        const float ep = getb(endc,   j, mode) ? 0.0f : NEGINF;

        float last_alpha = 0.0f;

        for (int c = 0; c <= nchunk; ++c) {
            barsync();   // chunk c resident + fused
            if (c >= nchunk) continue;
            const char* slot = (const char*)buf + (size_t)(c & (NS - 1)) * CHUNK_B;

            int t0 = c * CH;
            int t1 = t0 + CH; if (t1 > len) t1 = len;

            if (c == 0) {
                // t=0 RAW phi (pair layout): alpha0[j] = max_i phi0[i][j] + sp (+ep if len==1)
                const float2* ph2 = (const float2*)slot + j;
                float2 e0 = ph2[0];
                float m = fmaxf(e0.x, e0.y);
#pragma unroll
                for (int p = 1; p < 16; ++p) {
                    float2 e = ph2[p * 32];
                    m = fmaxf(m, fmaxf(e.x, e.y));
                }
                last_alpha = m + sp;
                if (len == 1) last_alpha += ep;
                aring[j] = last_alpha;   // slot 0
                t0 = 1;
            }

            int tend = t1 < lenm1 ? t1 : lenm1;
#pragma unroll 2
            for (int t = t0; t < tend; ++t) {
                const float2* ph2 = (const float2*)(slot + (size_t)(t & (CH - 1)) * 4096) + j;
                float a[NTAG];
                load_alpha(aring + ((t - 1) & (ARING - 1)) * NTAG, a);
                last_alpha = vval<false>(ph2, a, ep);
                aring[(t & (ARING - 1)) * NTAG + j] = last_alpha;
            }

            if (len >= 2 && (lenm1 >> 3) == c) {
                const float2* ph2 = (const float2*)(slot + (size_t)(lenm1 & (CH - 1)) * 4096) + j;
                float a[NTAG];
                load_alpha(aring + ((lenm1 - 1) & (ARING - 1)) * NTAG, a);
                last_alpha = vval<true>(ph2, a, ep);
                aring[(lenm1 & (ARING - 1)) * NTAG + j] = last_alpha;
            }
        }

        // final max / first-argmax over tags
        float v = last_alpha; int ix = j;
#pragma unroll
        for (int off = 16; off; off >>= 1) {
            float ov = __shfl_xor_sync(FULL, v, off);
            int   oi = __shfl_xor_sync(FULL, ix, off);
            if (ov > v || (ov == v && oi < ix)) { v = ov; ix = oi; }
        }
        if (j == 0) { out[b] = v; *xsh = ix; }
        barsync();  // final output handoff
    } else if (wid == 4) {
        // ============ idle warp: barrier participation only ============
        for (int c = 0; c <= nchunk; ++c) barsync();
        barsync();
    } else {
        // ============ argmax warps (wid 1,2,5,6): backpointers, 1 chunk behind ============
        const float ep = getb(endc, j, mode) ? 0.0f : NEGINF;
        const int quarter = (wid == 1) ? 0 : (wid == 2) ? 1 : (wid == 5) ? 2 : 3;

        for (int c = 0; c <= nchunk; ++c) {
            barsync();
            int cc = c - 1;
            if (cc < 0) continue;
            const char* slot = (const char*)buf + (size_t)(cc & (NS - 1)) * CHUNK_B;

            int base = cc * CH + quarter * 2;
            int t0 = base; if (t0 < 1) t0 = 1;
            int t1 = base + 2; if (t1 > len) t1 = len;
            int tend = t1 < lenm1 ? t1 : lenm1;

#pragma unroll 2
            for (int t = t0; t < tend; ++t) {
                const float2* ph2 = (const float2*)(slot + (size_t)(t & (CH - 1)) * 4096) + j;
                float a[NTAG];
                load_alpha(aring + ((t - 1) & (ARING - 1)) * NTAG, a);
                int bi = vidx<false>(ph2, a, ep);
                back[(size_t)t * NTAG + j] = (uint8_t)bi;
            }

            if (len >= 2 && (lenm1 >> 3) == cc && (((lenm1 & 7) >> 1) == quarter)) {
                const float2* ph2 = (const float2*)(slot + (size_t)(lenm1 & (CH - 1)) * 4096) + j;
                float a[NTAG];
                load_alpha(aring + ((lenm1 - 1) & (ARING - 1)) * NTAG, a);
                int bi = vidx<true>(ph2, a, ep);
                back[(size_t)lenm1 * NTAG + j] = (uint8_t)bi;
            }
        }

        barsync();  // xsh + back complete

        float* out_tags = out + B;   // [B, T]
        if (wid == 2) {
            for (int k = len + j; k < T; k += 32)
                out_tags[(size_t)b * T + k] = -1.0f;
        } else if (wid == 1 && j == 0) {
            int tag = *xsh;
            out_tags[(size_t)b * T + lenm1] = (float)tag;
            for (int tt = lenm1; tt >= 1; --tt) {
                tag = back[(size_t)tt * NTAG + tag];
                out_tags[(size_t)b * T + tt - 1] = (float)tag;
            }
        }
    }
}

extern "C" void kernel_launch(void* const* d_in, const int* in_sizes, int n_in,
                              void* d_out, int out_size)
{
    const float* lp   = (const float*)d_in[0];
    const void*  mask = d_in[1];
    const void*  sc   = d_in[2];
    const void*  ec   = d_in[3];
    const void*  tc   = d_in[4];

    const int BT = in_sizes[1];      // B*T elements in mask
    int B = out_size - BT;           // out = [B] mlp + [B*T] tags
    if (B <= 0) B = 64;
    const int T = BT / B;

    size_t smem = (size_t)NS * CHUNK_B + (size_t)ARING * NTAG * 4
                + (size_t)T * NTAG + 64;
    cudaFuncSetAttribute(ConstrainedDecoder_kernel,
                         cudaFuncAttributeMaxDynamicSharedMemorySize, (int)smem);

    ConstrainedDecoder_kernel<<<B, 256, smem>>>(lp, mask, sc, ec, tc,
                                                (float*)d_out, B, T);
}